// round 10
// baseline (speedup 1.0000x reference)
#include <cuda_runtime.h>
#include <cstdint>

#define USER_N 100000
#define ITEM_N 200000
#define NN     (USER_N + ITEM_N)   // 300000
#define D      64
#define E_NUM  4800000

#define SCAN_BS 512
#define SCAN_NB ((NN + SCAN_BS - 1) / SCAN_BS)   // 586

// ---- static device scratch ----
__device__ float g_Y1[(size_t)NN * D];
__device__ float g_Y2[(size_t)NN * D];
__device__ float g_Y3[(size_t)NN * D];
__device__ int2  g_cv[E_NUM];             // (col, val-bits) in CSR order
__device__ int   g_counts[NN];
__device__ int   g_offsets[NN];
__device__ int   g_cursor[NN];
__device__ int   g_blockSums[SCAN_NB];

// ---------------------------------------------------------------------------
__global__ void zero_counts_kernel(int* __restrict__ counts) {
    unsigned i = blockIdx.x * blockDim.x + threadIdx.x;
    if (i < (unsigned)NN) counts[i] = 0;
}

__global__ void hist_kernel(const int* __restrict__ rows, int* __restrict__ counts) {
    unsigned e = blockIdx.x * blockDim.x + threadIdx.x;
    if (e >= E_NUM) return;
    atomicAdd(counts + __ldg(rows + e), 1);
}

// ---- 3-kernel exclusive scan of counts -> offsets ----
__global__ void scan1_kernel(const int* __restrict__ counts,
                             int* __restrict__ offsets,
                             int* __restrict__ blockSums) {
    __shared__ int sh[SCAN_BS];
    int t = threadIdx.x;
    int i = blockIdx.x * SCAN_BS + t;
    int v = (i < NN) ? counts[i] : 0;
    sh[t] = v;
    __syncthreads();
    for (int ofs = 1; ofs < SCAN_BS; ofs <<= 1) {
        int add = (t >= ofs) ? sh[t - ofs] : 0;
        __syncthreads();
        sh[t] += add;
        __syncthreads();
    }
    if (i < NN) offsets[i] = sh[t] - v;
    if (t == SCAN_BS - 1) blockSums[blockIdx.x] = sh[t];
}

__global__ void scan2_kernel(int* __restrict__ blockSums) {
    __shared__ int sh[1024];
    int t = threadIdx.x;
    int v = (t < SCAN_NB) ? blockSums[t] : 0;
    sh[t] = v;
    __syncthreads();
    for (int ofs = 1; ofs < 1024; ofs <<= 1) {
        int add = (t >= ofs) ? sh[t - ofs] : 0;
        __syncthreads();
        sh[t] += add;
        __syncthreads();
    }
    if (t < SCAN_NB) blockSums[t] = sh[t] - v;
}

__global__ void scan3_kernel(int* __restrict__ offsets,
                             const int* __restrict__ blockSums,
                             int* __restrict__ cursor) {
    int i = blockIdx.x * SCAN_BS + threadIdx.x;
    if (i >= NN) return;
    int o = offsets[i] + blockSums[blockIdx.x];
    offsets[i] = o;
    cursor[i]  = o;
}

__global__ void scatter_kernel(const int* __restrict__ rows,
                               const int* __restrict__ cols,
                               const float* __restrict__ vals,
                               int* __restrict__ cursor,
                               int2* __restrict__ cv) {
    unsigned e = blockIdx.x * blockDim.x + threadIdx.x;
    if (e >= E_NUM) return;
    int r = __ldg(rows + e);
    int pos = atomicAdd(cursor + r, 1);
    __stcs(cv + pos, make_int2(__ldg(cols + e), __float_as_int(__ldg(vals + e))));
}

// ---------------------------------------------------------------------------
// CSR SpMM v4: warp per row, 4 edges per iteration, 2 independent gathers
// per lane per iteration (MLP=2 on the critical L2 path).
//   half = lane>>4 ; q = lane&15 (float4 slot of the 256B row)
//   iteration j: low half-warp handles edges j, j+2 ; high half j+1, j+3
//   1 shfl-instr per edge (lane-dependent source index jj = j + half).
// Epilogue: write y only (no acc RMW).
// SPLIT_X: layer-1 gathers straight from uEmb/iEmb.
// ---------------------------------------------------------------------------
template <bool SPLIT_X>
__global__ void __launch_bounds__(256)
csr_spmm_kernel(const int* __restrict__ off,
                const int* __restrict__ cnt,
                const int2* __restrict__ cv,
                const float4* __restrict__ x,     // [NN][16] float4
                const float4* __restrict__ xu,
                const float4* __restrict__ xi,
                float4* __restrict__ y) {
    unsigned warpId = (blockIdx.x * blockDim.x + threadIdx.x) >> 5;
    if (warpId >= (unsigned)NN) return;
    const unsigned lane = threadIdx.x & 31u;
    const unsigned half = lane >> 4;
    const unsigned q    = lane & 15u;
    const unsigned row  = warpId;

    int start = __ldg(off + row);
    int n     = __ldg(cnt + row);

    float4 s = make_float4(0.f, 0.f, 0.f, 0.f);

    for (int base = 0; base < n; base += 32) {
        int k = base + (int)lane;
        int2 pr = make_int2(0, 0);          // zero-pad: val 0, col 0 (hot)
        if (k < n) pr = __ldcs(cv + start + k);
        int m = min(32, n - base);
        #pragma unroll 8
        for (int j = 0; j < m; j += 4) {
            int jj = j + (int)half;
            int   c0 = __shfl_sync(0xffffffffu, pr.x, jj);
            float v0 = __int_as_float(__shfl_sync(0xffffffffu, pr.y, jj));
            int   c1 = __shfl_sync(0xffffffffu, pr.x, jj + 2);
            float v1 = __int_as_float(__shfl_sync(0xffffffffu, pr.y, jj + 2));
            const float4 *p0, *p1;
            if (SPLIT_X) {
                p0 = (c0 < USER_N) ? (xu + (size_t)c0 * 16)
                                   : (xi + (size_t)(c0 - USER_N) * 16);
                p1 = (c1 < USER_N) ? (xu + (size_t)c1 * 16)
                                   : (xi + (size_t)(c1 - USER_N) * 16);
            } else {
                p0 = x + (size_t)c0 * 16;
                p1 = x + (size_t)c1 * 16;
            }
            float4 a = __ldcg(p0 + q);       // two independent gathers in flight
            float4 b = __ldcg(p1 + q);
            s.x += v0 * a.x; s.y += v0 * a.y; s.z += v0 * a.z; s.w += v0 * a.w;
            s.x += v1 * b.x; s.y += v1 * b.y; s.z += v1 * b.z; s.w += v1 * b.w;
        }
    }

    // merge the two half-warp accumulators
    s.x += __shfl_xor_sync(0xffffffffu, s.x, 16);
    s.y += __shfl_xor_sync(0xffffffffu, s.y, 16);
    s.z += __shfl_xor_sync(0xffffffffu, s.z, 16);
    s.w += __shfl_xor_sync(0xffffffffu, s.w, 16);

    if (lane < 16) y[(size_t)row * 16 + q] = s;
}

// ---------------------------------------------------------------------------
// merge: out = X0 + Y1 + Y2 + Y3
// ---------------------------------------------------------------------------
__global__ void merge_kernel(const float4* __restrict__ u,
                             const float4* __restrict__ i,
                             const float4* __restrict__ y1,
                             const float4* __restrict__ y2,
                             const float4* __restrict__ y3,
                             float4* __restrict__ out) {
    const unsigned total = NN * 16;
    const unsigned usplit = USER_N * 16;
    unsigned idx = blockIdx.x * blockDim.x + threadIdx.x;
    if (idx >= total) return;
    float4 a = (idx < usplit) ? __ldg(u + idx) : __ldg(i + idx - usplit);
    float4 b = y1[idx];
    float4 c = y2[idx];
    float4 d = y3[idx];
    a.x += b.x + c.x + d.x;
    a.y += b.y + c.y + d.y;
    a.z += b.z + c.z + d.z;
    a.w += b.w + c.w + d.w;
    out[idx] = a;
}

extern "C" void kernel_launch(void* const* d_in, const int* in_sizes, int n_in,
                              void* d_out, int out_size) {
    const int*   rows = (const int*)  d_in[0];
    const int*   cols = (const int*)  d_in[1];
    const float* vals = (const float*)d_in[2];
    const float* uEmb = (const float*)d_in[3];
    const float* iEmb = (const float*)d_in[4];
    float* out = (float*)d_out;

    float* Y1;     cudaGetSymbolAddress((void**)&Y1,     g_Y1);
    float* Y2;     cudaGetSymbolAddress((void**)&Y2,     g_Y2);
    float* Y3;     cudaGetSymbolAddress((void**)&Y3,     g_Y3);
    int2*  cv;     cudaGetSymbolAddress((void**)&cv,     g_cv);
    int*   counts; cudaGetSymbolAddress((void**)&counts, g_counts);
    int*   offs;   cudaGetSymbolAddress((void**)&offs,   g_offsets);
    int*   cursor; cudaGetSymbolAddress((void**)&cursor, g_cursor);
    int*   bsums;  cudaGetSymbolAddress((void**)&bsums,  g_blockSums);

    const int T = 256;
    const int gridN     = (NN + T - 1) / T;
    const int gridE     = (E_NUM + T - 1) / T;
    const int gridSpmm  = (NN * 32 + T - 1) / T;          // warp per row
    const int gridMerge = (NN * 16 + T - 1) / T;

    const float4* u4 = (const float4*)uEmb;
    const float4* i4 = (const float4*)iEmb;

    // ---- build CSR ----
    zero_counts_kernel<<<gridN, T>>>(counts);
    hist_kernel<<<gridE, T>>>(rows, counts);
    scan1_kernel<<<SCAN_NB, SCAN_BS>>>(counts, offs, bsums);
    scan2_kernel<<<1, 1024>>>(bsums);
    scan3_kernel<<<SCAN_NB, SCAN_BS>>>(offs, bsums, cursor);
    scatter_kernel<<<gridE, T>>>(rows, cols, vals, cursor, cv);

    // ---- 3 propagation layers (write-only epilogues) ----
    csr_spmm_kernel<true ><<<gridSpmm, T>>>(offs, counts, cv,
        nullptr, u4, i4, (float4*)Y1);
    csr_spmm_kernel<false><<<gridSpmm, T>>>(offs, counts, cv,
        (const float4*)Y1, nullptr, nullptr, (float4*)Y2);
    csr_spmm_kernel<false><<<gridSpmm, T>>>(offs, counts, cv,
        (const float4*)Y2, nullptr, nullptr, (float4*)Y3);

    // ---- out = X0 + Y1 + Y2 + Y3 ----
    merge_kernel<<<gridMerge, T>>>(u4, i4,
        (const float4*)Y1, (const float4*)Y2, (const float4*)Y3, (float4*)out);
}

// round 11
// speedup vs baseline: 1.0017x; 1.0017x over previous
#include <cuda_runtime.h>
#include <cstdint>

#define USER_N 100000
#define ITEM_N 200000
#define NN     (USER_N + ITEM_N)   // 300000
#define D      64
#define E_NUM  4800000

#define SCAN_BS 512
#define SCAN_NB ((NN + SCAN_BS - 1) / SCAN_BS)   // 586

// ---- static device scratch ----
__device__ float g_Y1[(size_t)NN * D];
__device__ float g_Y2[(size_t)NN * D];
__device__ float g_Y3[(size_t)NN * D];
__device__ int2  g_cv[E_NUM];             // (col, val-bits) in CSR order
__device__ int   g_counts[NN];
__device__ int   g_offsets[NN];
__device__ int   g_cursor[NN];
__device__ int   g_blockSums[SCAN_NB];

// ---------------------------------------------------------------------------
__global__ void zero_counts_kernel(int* __restrict__ counts) {
    unsigned i = blockIdx.x * blockDim.x + threadIdx.x;
    if (i < (unsigned)NN) counts[i] = 0;
}

__global__ void hist_kernel(const int* __restrict__ rows, int* __restrict__ counts) {
    unsigned e = blockIdx.x * blockDim.x + threadIdx.x;
    if (e >= E_NUM) return;
    atomicAdd(counts + __ldg(rows + e), 1);
}

// ---- 3-kernel exclusive scan of counts -> offsets ----
__global__ void scan1_kernel(const int* __restrict__ counts,
                             int* __restrict__ offsets,
                             int* __restrict__ blockSums) {
    __shared__ int sh[SCAN_BS];
    int t = threadIdx.x;
    int i = blockIdx.x * SCAN_BS + t;
    int v = (i < NN) ? counts[i] : 0;
    sh[t] = v;
    __syncthreads();
    for (int ofs = 1; ofs < SCAN_BS; ofs <<= 1) {
        int add = (t >= ofs) ? sh[t - ofs] : 0;
        __syncthreads();
        sh[t] += add;
        __syncthreads();
    }
    if (i < NN) offsets[i] = sh[t] - v;
    if (t == SCAN_BS - 1) blockSums[blockIdx.x] = sh[t];
}

__global__ void scan2_kernel(int* __restrict__ blockSums) {
    __shared__ int sh[1024];
    int t = threadIdx.x;
    int v = (t < SCAN_NB) ? blockSums[t] : 0;
    sh[t] = v;
    __syncthreads();
    for (int ofs = 1; ofs < 1024; ofs <<= 1) {
        int add = (t >= ofs) ? sh[t - ofs] : 0;
        __syncthreads();
        sh[t] += add;
        __syncthreads();
    }
    if (t < SCAN_NB) blockSums[t] = sh[t] - v;
}

__global__ void scan3_kernel(int* __restrict__ offsets,
                             const int* __restrict__ blockSums,
                             int* __restrict__ cursor) {
    int i = blockIdx.x * SCAN_BS + threadIdx.x;
    if (i >= NN) return;
    int o = offsets[i] + blockSums[blockIdx.x];
    offsets[i] = o;
    cursor[i]  = o;
}

__global__ void scatter_kernel(const int* __restrict__ rows,
                               const int* __restrict__ cols,
                               const float* __restrict__ vals,
                               int* __restrict__ cursor,
                               int2* __restrict__ cv) {
    unsigned e = blockIdx.x * blockDim.x + threadIdx.x;
    if (e >= E_NUM) return;
    int r = __ldg(rows + e);
    int pos = atomicAdd(cursor + r, 1);
    __stcs(cv + pos, make_int2(__ldg(cols + e), __float_as_int(__ldg(vals + e))));
}

// ---------------------------------------------------------------------------
// CSR SpMM v4: warp per row, 4 edges per iteration, 2 independent gathers
// per lane per iteration (MLP=2 on the critical L2 path).
//   half = lane>>4 ; q = lane&15 (float4 slot of the 256B row)
//   iteration j: low half-warp handles edges j, j+2 ; high half j+1, j+3
//   1 shfl-instr per edge (lane-dependent source index jj = j + half).
// Epilogue: write y only (no acc RMW).
// SPLIT_X: layer-1 gathers straight from uEmb/iEmb.
// ---------------------------------------------------------------------------
template <bool SPLIT_X>
__global__ void __launch_bounds__(256)
csr_spmm_kernel(const int* __restrict__ off,
                const int* __restrict__ cnt,
                const int2* __restrict__ cv,
                const float4* __restrict__ x,     // [NN][16] float4
                const float4* __restrict__ xu,
                const float4* __restrict__ xi,
                float4* __restrict__ y) {
    unsigned warpId = (blockIdx.x * blockDim.x + threadIdx.x) >> 5;
    if (warpId >= (unsigned)NN) return;
    const unsigned lane = threadIdx.x & 31u;
    const unsigned half = lane >> 4;
    const unsigned q    = lane & 15u;
    const unsigned row  = warpId;

    int start = __ldg(off + row);
    int n     = __ldg(cnt + row);

    float4 s = make_float4(0.f, 0.f, 0.f, 0.f);

    for (int base = 0; base < n; base += 32) {
        int k = base + (int)lane;
        int2 pr = make_int2(0, 0);          // zero-pad: val 0, col 0 (hot)
        if (k < n) pr = __ldcs(cv + start + k);
        int m = min(32, n - base);
        #pragma unroll 8
        for (int j = 0; j < m; j += 4) {
            int jj = j + (int)half;
            int   c0 = __shfl_sync(0xffffffffu, pr.x, jj);
            float v0 = __int_as_float(__shfl_sync(0xffffffffu, pr.y, jj));
            int   c1 = __shfl_sync(0xffffffffu, pr.x, jj + 2);
            float v1 = __int_as_float(__shfl_sync(0xffffffffu, pr.y, jj + 2));
            const float4 *p0, *p1;
            if (SPLIT_X) {
                p0 = (c0 < USER_N) ? (xu + (size_t)c0 * 16)
                                   : (xi + (size_t)(c0 - USER_N) * 16);
                p1 = (c1 < USER_N) ? (xu + (size_t)c1 * 16)
                                   : (xi + (size_t)(c1 - USER_N) * 16);
            } else {
                p0 = x + (size_t)c0 * 16;
                p1 = x + (size_t)c1 * 16;
            }
            float4 a = __ldcg(p0 + q);       // two independent gathers in flight
            float4 b = __ldcg(p1 + q);
            s.x += v0 * a.x; s.y += v0 * a.y; s.z += v0 * a.z; s.w += v0 * a.w;
            s.x += v1 * b.x; s.y += v1 * b.y; s.z += v1 * b.z; s.w += v1 * b.w;
        }
    }

    // merge the two half-warp accumulators
    s.x += __shfl_xor_sync(0xffffffffu, s.x, 16);
    s.y += __shfl_xor_sync(0xffffffffu, s.y, 16);
    s.z += __shfl_xor_sync(0xffffffffu, s.z, 16);
    s.w += __shfl_xor_sync(0xffffffffu, s.w, 16);

    if (lane < 16) y[(size_t)row * 16 + q] = s;
}

// ---------------------------------------------------------------------------
// merge: out = X0 + Y1 + Y2 + Y3
// ---------------------------------------------------------------------------
__global__ void merge_kernel(const float4* __restrict__ u,
                             const float4* __restrict__ i,
                             const float4* __restrict__ y1,
                             const float4* __restrict__ y2,
                             const float4* __restrict__ y3,
                             float4* __restrict__ out) {
    const unsigned total = NN * 16;
    const unsigned usplit = USER_N * 16;
    unsigned idx = blockIdx.x * blockDim.x + threadIdx.x;
    if (idx >= total) return;
    float4 a = (idx < usplit) ? __ldg(u + idx) : __ldg(i + idx - usplit);
    float4 b = y1[idx];
    float4 c = y2[idx];
    float4 d = y3[idx];
    a.x += b.x + c.x + d.x;
    a.y += b.y + c.y + d.y;
    a.z += b.z + c.z + d.z;
    a.w += b.w + c.w + d.w;
    out[idx] = a;
}

extern "C" void kernel_launch(void* const* d_in, const int* in_sizes, int n_in,
                              void* d_out, int out_size) {
    const int*   rows = (const int*)  d_in[0];
    const int*   cols = (const int*)  d_in[1];
    const float* vals = (const float*)d_in[2];
    const float* uEmb = (const float*)d_in[3];
    const float* iEmb = (const float*)d_in[4];
    float* out = (float*)d_out;

    float* Y1;     cudaGetSymbolAddress((void**)&Y1,     g_Y1);
    float* Y2;     cudaGetSymbolAddress((void**)&Y2,     g_Y2);
    float* Y3;     cudaGetSymbolAddress((void**)&Y3,     g_Y3);
    int2*  cv;     cudaGetSymbolAddress((void**)&cv,     g_cv);
    int*   counts; cudaGetSymbolAddress((void**)&counts, g_counts);
    int*   offs;   cudaGetSymbolAddress((void**)&offs,   g_offsets);
    int*   cursor; cudaGetSymbolAddress((void**)&cursor, g_cursor);
    int*   bsums;  cudaGetSymbolAddress((void**)&bsums,  g_blockSums);

    const int T = 256;
    const int gridN     = (NN + T - 1) / T;
    const int gridE     = (E_NUM + T - 1) / T;
    const int gridSpmm  = (NN * 32 + T - 1) / T;          // warp per row
    const int gridMerge = (NN * 16 + T - 1) / T;

    const float4* u4 = (const float4*)uEmb;
    const float4* i4 = (const float4*)iEmb;

    // ---- build CSR ----
    zero_counts_kernel<<<gridN, T>>>(counts);
    hist_kernel<<<gridE, T>>>(rows, counts);
    scan1_kernel<<<SCAN_NB, SCAN_BS>>>(counts, offs, bsums);
    scan2_kernel<<<1, 1024>>>(bsums);
    scan3_kernel<<<SCAN_NB, SCAN_BS>>>(offs, bsums, cursor);
    scatter_kernel<<<gridE, T>>>(rows, cols, vals, cursor, cv);

    // ---- 3 propagation layers (write-only epilogues) ----
    csr_spmm_kernel<true ><<<gridSpmm, T>>>(offs, counts, cv,
        nullptr, u4, i4, (float4*)Y1);
    csr_spmm_kernel<false><<<gridSpmm, T>>>(offs, counts, cv,
        (const float4*)Y1, nullptr, nullptr, (float4*)Y2);
    csr_spmm_kernel<false><<<gridSpmm, T>>>(offs, counts, cv,
        (const float4*)Y2, nullptr, nullptr, (float4*)Y3);

    // ---- out = X0 + Y1 + Y2 + Y3 ----
    merge_kernel<<<gridMerge, T>>>(u4, i4,
        (const float4*)Y1, (const float4*)Y2, (const float4*)Y3, (float4*)out);
}